// round 1
// baseline (speedup 1.0000x reference)
#include <cuda_runtime.h>
#include <math.h>

#define Bb   2
#define Tt   2048
#define Dd   2048
#define Hh   32
#define HDh  64
#define Mtot (Bb*Tt)   // 4096

// Scratch buffers (allocation-free rule: __device__ globals)
__device__ float g_q[(size_t)Mtot * Dd];
__device__ float g_k[(size_t)Mtot * Dd];
__device__ float g_v[(size_t)Mtot * Dd];
__device__ float g_ctx[(size_t)Mtot * Dd];

// ---------------------------------------------------------------------------
// SGEMM: C[M,N] = A[M,K] @ B[N,K]^T + bias[N]   (fp32, NT layout)
// 128x128 CTA tile, BK=16, 256 threads, 8x8 register microtile.
// M,N,K assumed multiples of 128 / 16 (true here: 4096/2048/2048).
// ---------------------------------------------------------------------------
__global__ __launch_bounds__(256) void sgemm_nt_bias(
    const float* __restrict__ A, const float* __restrict__ Bm,
    const float* __restrict__ bias, float* __restrict__ C,
    int M, int N, int K)
{
    __shared__ float As[16][128];   // [k][m]
    __shared__ float Bs[16][128];   // [k][n]

    const int tid = threadIdx.x;
    const int tx  = tid & 15;       // 0..15 -> n
    const int ty  = tid >> 4;       // 0..15 -> m
    const int m0  = blockIdx.y * 128;
    const int n0  = blockIdx.x * 128;

    const float* Aptr = A  + (size_t)m0 * K;
    const float* Bptr = Bm + (size_t)n0 * K;

    float acc[8][8];
#pragma unroll
    for (int i = 0; i < 8; i++)
#pragma unroll
        for (int j = 0; j < 8; j++) acc[i][j] = 0.f;

    for (int k0 = 0; k0 < K; k0 += 16) {
        // Load 128x16 tiles of A and B, store transposed [k][row]
#pragma unroll
        for (int i = 0; i < 2; i++) {
            int idx = i * 256 + tid;        // 0..511
            int row = idx >> 2;             // 0..127
            int c4  = (idx & 3) * 4;        // 0,4,8,12
            float4 av = *(const float4*)(Aptr + (size_t)row * K + k0 + c4);
            As[c4+0][row] = av.x; As[c4+1][row] = av.y;
            As[c4+2][row] = av.z; As[c4+3][row] = av.w;
            float4 bv = *(const float4*)(Bptr + (size_t)row * K + k0 + c4);
            Bs[c4+0][row] = bv.x; Bs[c4+1][row] = bv.y;
            Bs[c4+2][row] = bv.z; Bs[c4+3][row] = bv.w;
        }
        __syncthreads();

#pragma unroll
        for (int kk = 0; kk < 16; kk++) {
            float a[8], b[8];
            *(float4*)&a[0] = *(const float4*)&As[kk][ty*8];
            *(float4*)&a[4] = *(const float4*)&As[kk][ty*8+4];
            *(float4*)&b[0] = *(const float4*)&Bs[kk][tx*8];
            *(float4*)&b[4] = *(const float4*)&Bs[kk][tx*8+4];
#pragma unroll
            for (int i = 0; i < 8; i++)
#pragma unroll
                for (int j = 0; j < 8; j++)
                    acc[i][j] += a[i] * b[j];
        }
        __syncthreads();
    }

    // Epilogue: += bias, vectorized store
#pragma unroll
    for (int i = 0; i < 8; i++) {
        int m = m0 + ty*8 + i;
#pragma unroll
        for (int j = 0; j < 8; j += 4) {
            int n = n0 + tx*8 + j;
            float4 r;
            r.x = acc[i][j+0] + bias[n+0];
            r.y = acc[i][j+1] + bias[n+1];
            r.z = acc[i][j+2] + bias[n+2];
            r.w = acc[i][j+3] + bias[n+3];
            *(float4*)(C + (size_t)m * N + n) = r;
        }
    }
}

// ---------------------------------------------------------------------------
// Flash attention, causal, fp32. One CTA per (b, h, 64-row q block).
// Layout of Q/K/V: [b*T + t, h*64 + d] (projection output, row stride D).
// 256 threads: tq = tid>>4 owns 4 q rows, tk = tid&15 owns 4 k cols / 4 dims.
// smem: Qs [d][rq] (pre-scaled), KP [d][ck] for K then reused as P [rq][ck],
//       Vs [ck][d].  3 * 16KB = 48KB.
// ---------------------------------------------------------------------------
__global__ __launch_bounds__(256) void flash_attn(
    const float* __restrict__ Q, const float* __restrict__ Kg,
    const float* __restrict__ Vg, float* __restrict__ Ctx)
{
    __shared__ float Qs[64][64];
    __shared__ float KP[64][64];
    __shared__ float Vs[64][64];

    const int tid = threadIdx.x;
    const int tk  = tid & 15;
    const int tq  = tid >> 4;
    const int qb  = blockIdx.x;          // 0..31
    const int bh  = blockIdx.y;          // 0..63
    const int b   = bh >> 5;
    const int h   = bh & 31;

    const size_t headoff = (size_t)h * HDh;
    const float* Qbase = Q  + ((size_t)(b*Tt + qb*64)) * Dd + headoff;
    const float* Kbase = Kg + ((size_t)(b*Tt)) * Dd + headoff;
    const float* Vbase = Vg + ((size_t)(b*Tt)) * Dd + headoff;
    const float scale = 0.125f;          // 1/sqrt(64)

    // Load Q block, transposed + pre-scaled
#pragma unroll
    for (int i = 0; i < 4; i++) {
        int idx = i * 256 + tid;         // 0..1023
        int row = idx >> 4;              // 0..63
        int c4  = (idx & 15) * 4;
        float4 qv = *(const float4*)(Qbase + (size_t)row * Dd + c4);
        Qs[c4+0][row] = qv.x * scale; Qs[c4+1][row] = qv.y * scale;
        Qs[c4+2][row] = qv.z * scale; Qs[c4+3][row] = qv.w * scale;
    }

    float o[4][4];
    float m_i[4], l_i[4];
#pragma unroll
    for (int i = 0; i < 4; i++) {
        m_i[i] = -INFINITY; l_i[i] = 0.f;
#pragma unroll
        for (int j = 0; j < 4; j++) o[i][j] = 0.f;
    }

    for (int kb = 0; kb <= qb; kb++) {
        __syncthreads();   // prev-iter reads of KP/Vs done; Qs visible (kb=0)

        // Load K (transposed) and V (direct)
#pragma unroll
        for (int i = 0; i < 4; i++) {
            int idx = i * 256 + tid;
            int row = idx >> 4;
            int c4  = (idx & 15) * 4;
            float4 kv = *(const float4*)(Kbase + ((size_t)(kb*64+row)) * Dd + c4);
            KP[c4+0][row] = kv.x; KP[c4+1][row] = kv.y;
            KP[c4+2][row] = kv.z; KP[c4+3][row] = kv.w;
            float4 vv = *(const float4*)(Vbase + ((size_t)(kb*64+row)) * Dd + c4);
            *(float4*)&Vs[row][c4] = vv;
        }
        __syncthreads();

        // S = (scaled Q) @ K^T for this 64x64 tile
        float s[4][4];
#pragma unroll
        for (int i = 0; i < 4; i++)
#pragma unroll
            for (int j = 0; j < 4; j++) s[i][j] = 0.f;

#pragma unroll 4
        for (int d = 0; d < 64; d++) {
            float4 qv = *(const float4*)&Qs[d][tq*4];
            float4 kv = *(const float4*)&KP[d][tk*4];
            float a[4] = {qv.x, qv.y, qv.z, qv.w};
            float bb[4] = {kv.x, kv.y, kv.z, kv.w};
#pragma unroll
            for (int i = 0; i < 4; i++)
#pragma unroll
                for (int j = 0; j < 4; j++)
                    s[i][j] += a[i] * bb[j];
        }

        // Causal mask (only diagonal block)
        if (kb == qb) {
#pragma unroll
            for (int i = 0; i < 4; i++)
#pragma unroll
                for (int j = 0; j < 4; j++)
                    if (tk*4 + j > tq*4 + i) s[i][j] = -INFINITY;
        }

        // Online softmax (row groups = 16 lanes with the same tq)
#pragma unroll
        for (int i = 0; i < 4; i++) {
            float mloc = fmaxf(fmaxf(s[i][0], s[i][1]), fmaxf(s[i][2], s[i][3]));
#pragma unroll
            for (int off = 8; off; off >>= 1)
                mloc = fmaxf(mloc, __shfl_xor_sync(0xffffffffu, mloc, off));
            float mnew  = fmaxf(m_i[i], mloc);
            float alpha = __expf(m_i[i] - mnew);
            float rs = 0.f;
#pragma unroll
            for (int j = 0; j < 4; j++) {
                float p = __expf(s[i][j] - mnew);
                s[i][j] = p;
                rs += p;
            }
#pragma unroll
            for (int off = 8; off; off >>= 1)
                rs += __shfl_xor_sync(0xffffffffu, rs, off);
            l_i[i] = l_i[i] * alpha + rs;
            m_i[i] = mnew;
#pragma unroll
            for (int j = 0; j < 4; j++) o[i][j] *= alpha;
        }

        __syncthreads();   // all warps done reading K from KP
        // Store P into KP as [rq][ck]
#pragma unroll
        for (int i = 0; i < 4; i++)
            *(float4*)&KP[tq*4+i][tk*4] = make_float4(s[i][0], s[i][1], s[i][2], s[i][3]);
        __syncthreads();

        // O += P @ V  (thread owns rows tq*4.., dims tk*4..)
#pragma unroll 2
        for (int ck = 0; ck < 64; ck++) {
            float4 vv = *(const float4*)&Vs[ck][tk*4];
            float vb[4] = {vv.x, vv.y, vv.z, vv.w};
#pragma unroll
            for (int i = 0; i < 4; i++) {
                float p = KP[tq*4+i][ck];
#pragma unroll
                for (int j = 0; j < 4; j++)
                    o[i][j] += p * vb[j];
            }
        }
    }

    // Normalize and write ctx
    float* Obase = Ctx + ((size_t)(b*Tt + qb*64)) * Dd + headoff;
#pragma unroll
    for (int i = 0; i < 4; i++) {
        float inv = 1.f / l_i[i];
        float4 r = make_float4(o[i][0]*inv, o[i][1]*inv, o[i][2]*inv, o[i][3]*inv);
        *(float4*)(Obase + (size_t)(tq*4+i) * Dd + tk*4) = r;
    }
}

// ---------------------------------------------------------------------------
extern "C" void kernel_launch(void* const* d_in, const int* in_sizes, int n_in,
                              void* d_out, int out_size)
{
    const float* x  = (const float*)d_in[0];
    const float* Wq = (const float*)d_in[1];
    const float* bq = (const float*)d_in[2];
    const float* Wk = (const float*)d_in[3];
    const float* bk = (const float*)d_in[4];
    const float* Wv = (const float*)d_in[5];
    const float* bv = (const float*)d_in[6];
    const float* Wo = (const float*)d_in[7];
    const float* bo = (const float*)d_in[8];
    float* out = (float*)d_out;

    float *q, *k, *v, *ctx;
    cudaGetSymbolAddress((void**)&q,   g_q);
    cudaGetSymbolAddress((void**)&k,   g_k);
    cudaGetSymbolAddress((void**)&v,   g_v);
    cudaGetSymbolAddress((void**)&ctx, g_ctx);

    dim3 gP(Dd/128, Mtot/128);   // (16, 32)
    sgemm_nt_bias<<<gP, 256>>>(x, Wq, bq, q, Mtot, Dd, Dd);
    sgemm_nt_bias<<<gP, 256>>>(x, Wk, bk, k, Mtot, Dd, Dd);
    sgemm_nt_bias<<<gP, 256>>>(x, Wv, bv, v, Mtot, Dd, Dd);

    dim3 gA(Tt/64, Bb*Hh);       // (32, 64)
    flash_attn<<<gA, 256>>>(q, k, v, ctx);

    sgemm_nt_bias<<<gP, 256>>>(ctx, Wo, bo, out, Mtot, Dd, Dd);
}

// round 4
// speedup vs baseline: 1.6614x; 1.6614x over previous
#include <cuda_runtime.h>
#include <cuda_bf16.h>
#include <math.h>
#include <stdint.h>

#define Bb   2
#define Tt   2048
#define Dd   2048
#define Hh   32
#define HDh  64
#define Mtot (Bb*Tt)   // 4096

// ---------------- scratch (__device__ globals; allocation-free rule) -------
__device__ float g_q[(size_t)Mtot * Dd];
__device__ float g_k[(size_t)Mtot * Dd];
__device__ float g_v[(size_t)Mtot * Dd];
__device__ float g_ctx[(size_t)Mtot * Dd];

__device__ __nv_bfloat16 g_xh[(size_t)Mtot * Dd];
__device__ __nv_bfloat16 g_xl[(size_t)Mtot * Dd];
__device__ __nv_bfloat16 g_ch[(size_t)Mtot * Dd];
__device__ __nv_bfloat16 g_cl[(size_t)Mtot * Dd];
__device__ __nv_bfloat16 g_wqh[(size_t)Dd * Dd];
__device__ __nv_bfloat16 g_wql[(size_t)Dd * Dd];
__device__ __nv_bfloat16 g_wkh[(size_t)Dd * Dd];
__device__ __nv_bfloat16 g_wkl[(size_t)Dd * Dd];
__device__ __nv_bfloat16 g_wvh[(size_t)Dd * Dd];
__device__ __nv_bfloat16 g_wvl[(size_t)Dd * Dd];
__device__ __nv_bfloat16 g_woh[(size_t)Dd * Dd];
__device__ __nv_bfloat16 g_wol[(size_t)Dd * Dd];

// ---------------- PTX helpers (baseline sm_100: no 'a' features) -----------
__device__ __forceinline__ uint32_t smem_u32(const void* p) {
    uint32_t a;
    asm("{ .reg .u64 t; cvta.to.shared.u64 t, %1; cvt.u32.u64 %0, t; }"
        : "=r"(a) : "l"(p));
    return a;
}

#define CP_ASYNC16(dst_u32, src_ptr) \
    asm volatile("cp.async.cg.shared.global [%0], [%1], 16;" \
                 :: "r"(dst_u32), "l"(src_ptr))
#define CP_COMMIT() asm volatile("cp.async.commit_group;")
#define CP_WAIT1()  asm volatile("cp.async.wait_group 1;")

#define LDM_X4(r0, r1, r2, r3, addr) \
    asm volatile("ldmatrix.sync.aligned.m8n8.x4.shared.b16 {%0,%1,%2,%3}, [%4];" \
                 : "=r"(r0), "=r"(r1), "=r"(r2), "=r"(r3) : "r"(addr))

#define MMA_BF16(d, a, b) \
    asm volatile("mma.sync.aligned.m16n8k16.row.col.f32.bf16.bf16.f32 " \
                 "{%0,%1,%2,%3},{%4,%5,%6,%7},{%8,%9},{%0,%1,%2,%3};" \
                 : "+f"((d)[0]), "+f"((d)[1]), "+f"((d)[2]), "+f"((d)[3]) \
                 : "r"((a)[0]), "r"((a)[1]), "r"((a)[2]), "r"((a)[3]), \
                   "r"((b)[0]), "r"((b)[1]))

// ---------------------------------------------------------------------------
// split fp32 -> (hi, lo) bf16.  n4 = element count / 4.
// ---------------------------------------------------------------------------
__global__ __launch_bounds__(256) void split_bf16(
    const float* __restrict__ x, __nv_bfloat16* __restrict__ hi,
    __nv_bfloat16* __restrict__ lo, int n4)
{
    int i = blockIdx.x * blockDim.x + threadIdx.x;
    if (i >= n4) return;
    float4 v = ((const float4*)x)[i];
    float vv[4] = {v.x, v.y, v.z, v.w};
    __nv_bfloat16 h[4], l[4];
#pragma unroll
    for (int j = 0; j < 4; j++) {
        h[j] = __float2bfloat16(vv[j]);
        l[j] = __float2bfloat16(vv[j] - __bfloat162float(h[j]));
    }
    ((uint2*)hi)[i] = *(uint2*)h;
    ((uint2*)lo)[i] = *(uint2*)l;
}

// ---------------------------------------------------------------------------
// Split-bf16 HMMA GEMM:  C[M,N] = A[M,K] @ B[N,K]^T + bias[N]
// 128x128 CTA tile, BK=32, 8 warps (4m x 2n), warp tile 32x64.
// smem rows padded to 80B (40 bf16): ldmatrix conflict-free without swizzle.
// Three mma passes per tile: hi*hi + hi*lo + lo*hi (fp32 accum).
// ---------------------------------------------------------------------------
#define BM 128
#define BN 128
#define BK 32
#define PITCH 40                            // bf16 elems per smem row (80 B)
#define TILE_B (128 * PITCH * 2)            // 10240 B per operand tile
#define STAGE_B (4 * TILE_B)                // Ah, Al, Bh, Bl
#define GEMM_SMEM (2 * STAGE_B)             // 81920 B

__global__ __launch_bounds__(256, 1) void gemm_split_mma(
    const __nv_bfloat16* __restrict__ Ah, const __nv_bfloat16* __restrict__ Al,
    const __nv_bfloat16* __restrict__ Bh, const __nv_bfloat16* __restrict__ Bl,
    const float* __restrict__ bias, float* __restrict__ C,
    int M, int N, int K)
{
    extern __shared__ char smem[];
    const uint32_t smem0 = smem_u32(smem);

    const int tid  = threadIdx.x;
    const int lane = tid & 31;
    const int wid  = tid >> 5;
    const int wm   = wid & 3;          // 0..3  -> 32-row slab
    const int wn   = wid >> 2;         // 0..1  -> 64-col slab
    const int m0   = blockIdx.y * BM;
    const int n0   = blockIdx.x * BN;

    const __nv_bfloat16* srcs[4] = {
        Ah + (size_t)m0 * K, Al + (size_t)m0 * K,
        Bh + (size_t)n0 * K, Bl + (size_t)n0 * K };

    // ldmatrix per-lane geometry
    const int a_r  = (lane & 7) + ((lane >> 3) & 1) * 8;  // row within 16
    const int a_k8 = (lane >> 4) * 8;                     // k offset 0/8
    const int b_n  = (lane & 7) + ((lane >> 4) ? 8 : 0);  // n within 16
    const int b_k8 = ((lane >> 3) & 1) * 8;

    float acc[2][8][4];
#pragma unroll
    for (int mt = 0; mt < 2; mt++)
#pragma unroll
        for (int nt = 0; nt < 8; nt++)
#pragma unroll
            for (int j = 0; j < 4; j++) acc[mt][nt][j] = 0.f;

    const int NC = K / BK;   // 64

    // per-thread load geometry (constant across iterations)
    const int ld_row0 = tid >> 2;          // 0..63
    const int ld_row1 = 64 + (tid >> 2);   // 64..127
    const int ld_ch   = (tid & 3) * 8;     // k element offset of 16B chunk
    const uint32_t ld_off0 = (uint32_t)ld_row0 * 80u + (uint32_t)(tid & 3) * 16u;
    const uint32_t ld_off1 = (uint32_t)ld_row1 * 80u + (uint32_t)(tid & 3) * 16u;

    // ---- prologue: stage 0 loads ----
#pragma unroll
    for (int t = 0; t < 4; t++) {
        const __nv_bfloat16* s = srcs[t];
        CP_ASYNC16(smem0 + t * TILE_B + ld_off0, s + (size_t)ld_row0 * K + ld_ch);
        CP_ASYNC16(smem0 + t * TILE_B + ld_off1, s + (size_t)ld_row1 * K + ld_ch);
    }
    CP_COMMIT();

    for (int kc = 0; kc < NC; kc++) {
        // issue next chunk into the other stage
        if (kc + 1 < NC) {
            const uint32_t st = smem0 + ((kc + 1) & 1) * STAGE_B;
            const int koff = (kc + 1) * BK + ld_ch;
#pragma unroll
            for (int t = 0; t < 4; t++) {
                const __nv_bfloat16* s = srcs[t];
                CP_ASYNC16(st + t * TILE_B + ld_off0, s + (size_t)ld_row0 * K + koff);
                CP_ASYNC16(st + t * TILE_B + ld_off1, s + (size_t)ld_row1 * K + koff);
            }
        }
        CP_COMMIT();
        CP_WAIT1();            // current chunk resident
        __syncthreads();

        const uint32_t stage = smem0 + (kc & 1) * STAGE_B;
        const uint32_t aBase = stage;                    // Ah; Al at +TILE_B
        const uint32_t bBase = stage + 2 * TILE_B;       // Bh; Bl at +TILE_B

#pragma unroll
        for (int ks = 0; ks < 2; ks++) {
            const int k0 = ks * 16;

            uint32_t ah[2][4], al[2][4];
#pragma unroll
            for (int mt = 0; mt < 2; mt++) {
                uint32_t addr = aBase + (uint32_t)(wm*32 + mt*16 + a_r) * 80u
                              + (uint32_t)(k0 + a_k8) * 2u;
                LDM_X4(ah[mt][0], ah[mt][1], ah[mt][2], ah[mt][3], addr);
                LDM_X4(al[mt][0], al[mt][1], al[mt][2], al[mt][3], addr + TILE_B);
            }

#pragma unroll
            for (int nt2 = 0; nt2 < 4; nt2++) {
                uint32_t bh[4], bl[4];
                uint32_t baddr = bBase + (uint32_t)(wn*64 + nt2*16 + b_n) * 80u
                               + (uint32_t)(k0 + b_k8) * 2u;
                LDM_X4(bh[0], bh[1], bh[2], bh[3], baddr);
                LDM_X4(bl[0], bl[1], bl[2], bl[3], baddr + TILE_B);

#pragma unroll
                for (int h = 0; h < 2; h++) {
                    uint32_t bfh[2] = { bh[2*h], bh[2*h + 1] };
                    uint32_t bfl[2] = { bl[2*h], bl[2*h + 1] };
                    const int nt = nt2 * 2 + h;
#pragma unroll
                    for (int mt = 0; mt < 2; mt++) {
                        MMA_BF16(acc[mt][nt], ah[mt], bfh);
                        MMA_BF16(acc[mt][nt], ah[mt], bfl);
                        MMA_BF16(acc[mt][nt], al[mt], bfh);
                    }
                }
            }
        }
        __syncthreads();
    }

    // ---- epilogue: + bias, store fp32 ----
    const int g  = lane >> 2;
    const int tI = lane & 3;
#pragma unroll
    for (int mt = 0; mt < 2; mt++) {
        const int row0 = m0 + wm*32 + mt*16 + g;
#pragma unroll
        for (int nt = 0; nt < 8; nt++) {
            const int col = n0 + wn*64 + nt*8 + tI*2;
            float2 bb = *(const float2*)&bias[col];
            float2 v0 = { acc[mt][nt][0] + bb.x, acc[mt][nt][1] + bb.y };
            float2 v1 = { acc[mt][nt][2] + bb.x, acc[mt][nt][3] + bb.y };
            *(float2*)(C + (size_t)row0       * N + col) = v0;
            *(float2*)(C + (size_t)(row0 + 8) * N + col) = v1;
        }
    }
}

// ---------------------------------------------------------------------------
// Flash attention, causal, fp32 (unchanged from passing round-1 kernel)
// ---------------------------------------------------------------------------
__global__ __launch_bounds__(256) void flash_attn(
    const float* __restrict__ Q, const float* __restrict__ Kg,
    const float* __restrict__ Vg, float* __restrict__ Ctx)
{
    __shared__ float Qs[64][64];
    __shared__ float KP[64][64];
    __shared__ float Vs[64][64];

    const int tid = threadIdx.x;
    const int tk  = tid & 15;
    const int tq  = tid >> 4;
    const int qb  = blockIdx.x;
    const int bh  = blockIdx.y;
    const int b   = bh >> 5;
    const int h   = bh & 31;

    const size_t headoff = (size_t)h * HDh;
    const float* Qbase = Q  + ((size_t)(b*Tt + qb*64)) * Dd + headoff;
    const float* Kbase = Kg + ((size_t)(b*Tt)) * Dd + headoff;
    const float* Vbase = Vg + ((size_t)(b*Tt)) * Dd + headoff;
    const float scale = 0.125f;

#pragma unroll
    for (int i = 0; i < 4; i++) {
        int idx = i * 256 + tid;
        int row = idx >> 4;
        int c4  = (idx & 15) * 4;
        float4 qv = *(const float4*)(Qbase + (size_t)row * Dd + c4);
        Qs[c4+0][row] = qv.x * scale; Qs[c4+1][row] = qv.y * scale;
        Qs[c4+2][row] = qv.z * scale; Qs[c4+3][row] = qv.w * scale;
    }

    float o[4][4];
    float m_i[4], l_i[4];
#pragma unroll
    for (int i = 0; i < 4; i++) {
        m_i[i] = -INFINITY; l_i[i] = 0.f;
#pragma unroll
        for (int j = 0; j < 4; j++) o[i][j] = 0.f;
    }

    for (int kb = 0; kb <= qb; kb++) {
        __syncthreads();

#pragma unroll
        for (int i = 0; i < 4; i++) {
            int idx = i * 256 + tid;
            int row = idx >> 4;
            int c4  = (idx & 15) * 4;
            float4 kv = *(const float4*)(Kbase + ((size_t)(kb*64+row)) * Dd + c4);
            KP[c4+0][row] = kv.x; KP[c4+1][row] = kv.y;
            KP[c4+2][row] = kv.z; KP[c4+3][row] = kv.w;
            float4 vv = *(const float4*)(Vbase + ((size_t)(kb*64+row)) * Dd + c4);
            *(float4*)&Vs[row][c4] = vv;
        }
        __syncthreads();

        float s[4][4];
#pragma unroll
        for (int i = 0; i < 4; i++)
#pragma unroll
            for (int j = 0; j < 4; j++) s[i][j] = 0.f;

#pragma unroll 4
        for (int d = 0; d < 64; d++) {
            float4 qv = *(const float4*)&Qs[d][tq*4];
            float4 kv = *(const float4*)&KP[d][tk*4];
            float a[4] = {qv.x, qv.y, qv.z, qv.w};
            float bb[4] = {kv.x, kv.y, kv.z, kv.w};
#pragma unroll
            for (int i = 0; i < 4; i++)
#pragma unroll
                for (int j = 0; j < 4; j++)
                    s[i][j] += a[i] * bb[j];
        }

        if (kb == qb) {
#pragma unroll
            for (int i = 0; i < 4; i++)
#pragma unroll
                for (int j = 0; j < 4; j++)
                    if (tk*4 + j > tq*4 + i) s[i][j] = -INFINITY;
        }

#pragma unroll
        for (int i = 0; i < 4; i++) {
            float mloc = fmaxf(fmaxf(s[i][0], s[i][1]), fmaxf(s[i][2], s[i][3]));
#pragma unroll
            for (int off = 8; off; off >>= 1)
                mloc = fmaxf(mloc, __shfl_xor_sync(0xffffffffu, mloc, off));
            float mnew  = fmaxf(m_i[i], mloc);
            float alpha = __expf(m_i[i] - mnew);
            float rs = 0.f;
#pragma unroll
            for (int j = 0; j < 4; j++) {
                float p = __expf(s[i][j] - mnew);
                s[i][j] = p;
                rs += p;
            }
#pragma unroll
            for (int off = 8; off; off >>= 1)
                rs += __shfl_xor_sync(0xffffffffu, rs, off);
            l_i[i] = l_i[i] * alpha + rs;
            m_i[i] = mnew;
#pragma unroll
            for (int j = 0; j < 4; j++) o[i][j] *= alpha;
        }

        __syncthreads();
#pragma unroll
        for (int i = 0; i < 4; i++)
            *(float4*)&KP[tq*4+i][tk*4] = make_float4(s[i][0], s[i][1], s[i][2], s[i][3]);
        __syncthreads();

#pragma unroll 2
        for (int ck = 0; ck < 64; ck++) {
            float4 vv = *(const float4*)&Vs[ck][tk*4];
            float vb[4] = {vv.x, vv.y, vv.z, vv.w};
#pragma unroll
            for (int i = 0; i < 4; i++) {
                float p = KP[tq*4+i][ck];
#pragma unroll
                for (int j = 0; j < 4; j++)
                    o[i][j] += p * vb[j];
            }
        }
    }

    float* Obase = Ctx + ((size_t)(b*Tt + qb*64)) * Dd + headoff;
#pragma unroll
    for (int i = 0; i < 4; i++) {
        float inv = 1.f / l_i[i];
        float4 r = make_float4(o[i][0]*inv, o[i][1]*inv, o[i][2]*inv, o[i][3]*inv);
        *(float4*)(Obase + (size_t)(tq*4+i) * Dd + tk*4) = r;
    }
}

// ---------------------------------------------------------------------------
extern "C" void kernel_launch(void* const* d_in, const int* in_sizes, int n_in,
                              void* d_out, int out_size)
{
    const float* x  = (const float*)d_in[0];
    const float* Wq = (const float*)d_in[1];
    const float* bq = (const float*)d_in[2];
    const float* Wk = (const float*)d_in[3];
    const float* bk = (const float*)d_in[4];
    const float* Wv = (const float*)d_in[5];
    const float* bv = (const float*)d_in[6];
    const float* Wo = (const float*)d_in[7];
    const float* bo = (const float*)d_in[8];
    float* out = (float*)d_out;

    float *q, *k, *v, *ctx;
    cudaGetSymbolAddress((void**)&q,   g_q);
    cudaGetSymbolAddress((void**)&k,   g_k);
    cudaGetSymbolAddress((void**)&v,   g_v);
    cudaGetSymbolAddress((void**)&ctx, g_ctx);

    __nv_bfloat16 *xh, *xl, *ch, *cl;
    __nv_bfloat16 *wqh, *wql, *wkh, *wkl, *wvh, *wvl, *woh, *wol;
    cudaGetSymbolAddress((void**)&xh, g_xh);   cudaGetSymbolAddress((void**)&xl, g_xl);
    cudaGetSymbolAddress((void**)&ch, g_ch);   cudaGetSymbolAddress((void**)&cl, g_cl);
    cudaGetSymbolAddress((void**)&wqh, g_wqh); cudaGetSymbolAddress((void**)&wql, g_wql);
    cudaGetSymbolAddress((void**)&wkh, g_wkh); cudaGetSymbolAddress((void**)&wkl, g_wkl);
    cudaGetSymbolAddress((void**)&wvh, g_wvh); cudaGetSymbolAddress((void**)&wvl, g_wvl);
    cudaGetSymbolAddress((void**)&woh, g_woh); cudaGetSymbolAddress((void**)&wol, g_wol);

    cudaFuncSetAttribute(gemm_split_mma,
                         cudaFuncAttributeMaxDynamicSharedMemorySize, GEMM_SMEM);

    const int nX4 = Mtot * Dd / 4;
    const int nW4 = Dd * Dd / 4;
    split_bf16<<<nX4 / 256, 256>>>(x,  xh,  xl,  nX4);
    split_bf16<<<nW4 / 256, 256>>>(Wq, wqh, wql, nW4);
    split_bf16<<<nW4 / 256, 256>>>(Wk, wkh, wkl, nW4);
    split_bf16<<<nW4 / 256, 256>>>(Wv, wvh, wvl, nW4);
    split_bf16<<<nW4 / 256, 256>>>(Wo, woh, wol, nW4);

    dim3 gP(Dd / BN, Mtot / BM);     // (16, 32)
    gemm_split_mma<<<gP, 256, GEMM_SMEM>>>(xh, xl, wqh, wql, bq, q, Mtot, Dd, Dd);
    gemm_split_mma<<<gP, 256, GEMM_SMEM>>>(xh, xl, wkh, wkl, bk, k, Mtot, Dd, Dd);
    gemm_split_mma<<<gP, 256, GEMM_SMEM>>>(xh, xl, wvh, wvl, bv, v, Mtot, Dd, Dd);

    dim3 gA(Tt / 64, Bb * Hh);       // (32, 64)
    flash_attn<<<gA, 256>>>(q, k, v, ctx);

    split_bf16<<<nX4 / 256, 256>>>(ctx, ch, cl, nX4);
    gemm_split_mma<<<gP, 256, GEMM_SMEM>>>(ch, cl, woh, wol, bo, out, Mtot, Dd, Dd);
}

// round 5
// speedup vs baseline: 2.5330x; 1.5246x over previous
#include <cuda_runtime.h>
#include <cuda_bf16.h>
#include <math.h>
#include <stdint.h>

#define Bb   2
#define Tt   2048
#define Dd   2048
#define Hh   32
#define HDh  64
#define Mtot (Bb*Tt)   // 4096

// ---------------- scratch (__device__ globals; allocation-free rule) -------
__device__ __nv_bfloat16 g_xh[(size_t)Mtot * Dd];
__device__ __nv_bfloat16 g_xl[(size_t)Mtot * Dd];
__device__ __nv_bfloat16 g_ch[(size_t)Mtot * Dd];
__device__ __nv_bfloat16 g_cl[(size_t)Mtot * Dd];
__device__ __nv_bfloat16 g_wqh[(size_t)Dd * Dd];
__device__ __nv_bfloat16 g_wql[(size_t)Dd * Dd];
__device__ __nv_bfloat16 g_wkh[(size_t)Dd * Dd];
__device__ __nv_bfloat16 g_wkl[(size_t)Dd * Dd];
__device__ __nv_bfloat16 g_wvh[(size_t)Dd * Dd];
__device__ __nv_bfloat16 g_wvl[(size_t)Dd * Dd];
__device__ __nv_bfloat16 g_woh[(size_t)Dd * Dd];
__device__ __nv_bfloat16 g_wol[(size_t)Dd * Dd];
// attention operand buffers (split bf16, written by GEMM epilogue)
__device__ __nv_bfloat16 g_aqh[(size_t)Mtot * Dd];
__device__ __nv_bfloat16 g_aql[(size_t)Mtot * Dd];
__device__ __nv_bfloat16 g_akh[(size_t)Mtot * Dd];
__device__ __nv_bfloat16 g_akl[(size_t)Mtot * Dd];
__device__ __nv_bfloat16 g_avh[(size_t)Mtot * Dd];
__device__ __nv_bfloat16 g_avl[(size_t)Mtot * Dd];

// ---------------- PTX helpers (baseline sm_100: no 'a' features) -----------
__device__ __forceinline__ uint32_t smem_u32(const void* p) {
    uint32_t a;
    asm("{ .reg .u64 t; cvta.to.shared.u64 t, %1; cvt.u32.u64 %0, t; }"
        : "=r"(a) : "l"(p));
    return a;
}

#define CP_ASYNC16(dst_u32, src_ptr) \
    asm volatile("cp.async.cg.shared.global [%0], [%1], 16;" \
                 :: "r"(dst_u32), "l"(src_ptr))
#define CP_COMMIT() asm volatile("cp.async.commit_group;")
#define CP_WAIT1()  asm volatile("cp.async.wait_group 1;")

#define LDM_X4(r0, r1, r2, r3, addr) \
    asm volatile("ldmatrix.sync.aligned.m8n8.x4.shared.b16 {%0,%1,%2,%3}, [%4];" \
                 : "=r"(r0), "=r"(r1), "=r"(r2), "=r"(r3) : "r"(addr))

#define LDM_X4_T(r0, r1, r2, r3, addr) \
    asm volatile("ldmatrix.sync.aligned.m8n8.x4.trans.shared.b16 {%0,%1,%2,%3}, [%4];" \
                 : "=r"(r0), "=r"(r1), "=r"(r2), "=r"(r3) : "r"(addr))

#define MMA_BF16(d, a, b) \
    asm volatile("mma.sync.aligned.m16n8k16.row.col.f32.bf16.bf16.f32 " \
                 "{%0,%1,%2,%3},{%4,%5,%6,%7},{%8,%9},{%0,%1,%2,%3};" \
                 : "+f"((d)[0]), "+f"((d)[1]), "+f"((d)[2]), "+f"((d)[3]) \
                 : "r"((a)[0]), "r"((a)[1]), "r"((a)[2]), "r"((a)[3]), \
                   "r"((b)[0]), "r"((b)[1]))

__device__ __forceinline__ float ex2f(float x) {
    float y;
    asm("ex2.approx.f32 %0, %1;" : "=f"(y) : "f"(x));
    return y;
}
__device__ __forceinline__ uint32_t packbf(float lo, float hi) {
    __nv_bfloat162 t = __floats2bfloat162_rn(lo, hi);  // .x = lo half
    return *(uint32_t*)&t;
}

// ---------------------------------------------------------------------------
// split fp32 -> (hi, lo) bf16.  n4 = element count / 4.
// ---------------------------------------------------------------------------
__global__ __launch_bounds__(256) void split_bf16(
    const float* __restrict__ x, __nv_bfloat16* __restrict__ hi,
    __nv_bfloat16* __restrict__ lo, int n4)
{
    int i = blockIdx.x * blockDim.x + threadIdx.x;
    if (i >= n4) return;
    float4 v = ((const float4*)x)[i];
    float vv[4] = {v.x, v.y, v.z, v.w};
    __nv_bfloat16 h[4], l[4];
#pragma unroll
    for (int j = 0; j < 4; j++) {
        h[j] = __float2bfloat16(vv[j]);
        l[j] = __float2bfloat16(vv[j] - __bfloat162float(h[j]));
    }
    ((uint2*)hi)[i] = *(uint2*)h;
    ((uint2*)lo)[i] = *(uint2*)l;
}

// ---------------------------------------------------------------------------
// Split-bf16 HMMA GEMM:  C = A @ B^T + bias.
// SPLIT=false: write fp32 C.   SPLIT=true: write (hi,lo) bf16 Ch/Cl.
// ---------------------------------------------------------------------------
#define BM 128
#define BN 128
#define BK 32
#define PITCH 40
#define TILE_B (128 * PITCH * 2)            // 10240
#define STAGE_B (4 * TILE_B)
#define GEMM_SMEM (2 * STAGE_B)             // 81920

template<bool SPLIT>
__global__ __launch_bounds__(256, 1) void gemm_split_mma(
    const __nv_bfloat16* __restrict__ Ah, const __nv_bfloat16* __restrict__ Al,
    const __nv_bfloat16* __restrict__ Bh, const __nv_bfloat16* __restrict__ Bl,
    const float* __restrict__ bias, float* __restrict__ C,
    __nv_bfloat16* __restrict__ Ch, __nv_bfloat16* __restrict__ Cl,
    int M, int N, int K)
{
    extern __shared__ char smem[];
    const uint32_t smem0 = smem_u32(smem);

    const int tid  = threadIdx.x;
    const int lane = tid & 31;
    const int wid  = tid >> 5;
    const int wm   = wid & 3;
    const int wn   = wid >> 2;
    const int m0   = blockIdx.y * BM;
    const int n0   = blockIdx.x * BN;

    const __nv_bfloat16* srcs[4] = {
        Ah + (size_t)m0 * K, Al + (size_t)m0 * K,
        Bh + (size_t)n0 * K, Bl + (size_t)n0 * K };

    const int a_r  = (lane & 7) + ((lane >> 3) & 1) * 8;
    const int a_k8 = (lane >> 4) * 8;
    const int b_n  = (lane & 7) + ((lane >> 4) ? 8 : 0);
    const int b_k8 = ((lane >> 3) & 1) * 8;

    float acc[2][8][4];
#pragma unroll
    for (int mt = 0; mt < 2; mt++)
#pragma unroll
        for (int nt = 0; nt < 8; nt++)
#pragma unroll
            for (int j = 0; j < 4; j++) acc[mt][nt][j] = 0.f;

    const int NC = K / BK;

    const int ld_row0 = tid >> 2;
    const int ld_row1 = 64 + (tid >> 2);
    const int ld_ch   = (tid & 3) * 8;
    const uint32_t ld_off0 = (uint32_t)ld_row0 * 80u + (uint32_t)(tid & 3) * 16u;
    const uint32_t ld_off1 = (uint32_t)ld_row1 * 80u + (uint32_t)(tid & 3) * 16u;

#pragma unroll
    for (int t = 0; t < 4; t++) {
        const __nv_bfloat16* s = srcs[t];
        CP_ASYNC16(smem0 + t * TILE_B + ld_off0, s + (size_t)ld_row0 * K + ld_ch);
        CP_ASYNC16(smem0 + t * TILE_B + ld_off1, s + (size_t)ld_row1 * K + ld_ch);
    }
    CP_COMMIT();

    for (int kc = 0; kc < NC; kc++) {
        if (kc + 1 < NC) {
            const uint32_t st = smem0 + ((kc + 1) & 1) * STAGE_B;
            const int koff = (kc + 1) * BK + ld_ch;
#pragma unroll
            for (int t = 0; t < 4; t++) {
                const __nv_bfloat16* s = srcs[t];
                CP_ASYNC16(st + t * TILE_B + ld_off0, s + (size_t)ld_row0 * K + koff);
                CP_ASYNC16(st + t * TILE_B + ld_off1, s + (size_t)ld_row1 * K + koff);
            }
        }
        CP_COMMIT();
        CP_WAIT1();
        __syncthreads();

        const uint32_t stage = smem0 + (kc & 1) * STAGE_B;
        const uint32_t aBase = stage;
        const uint32_t bBase = stage + 2 * TILE_B;

#pragma unroll
        for (int ks = 0; ks < 2; ks++) {
            const int k0 = ks * 16;

            uint32_t ah[2][4], al[2][4];
#pragma unroll
            for (int mt = 0; mt < 2; mt++) {
                uint32_t addr = aBase + (uint32_t)(wm*32 + mt*16 + a_r) * 80u
                              + (uint32_t)(k0 + a_k8) * 2u;
                LDM_X4(ah[mt][0], ah[mt][1], ah[mt][2], ah[mt][3], addr);
                LDM_X4(al[mt][0], al[mt][1], al[mt][2], al[mt][3], addr + TILE_B);
            }

#pragma unroll
            for (int nt2 = 0; nt2 < 4; nt2++) {
                uint32_t bh[4], bl[4];
                uint32_t baddr = bBase + (uint32_t)(wn*64 + nt2*16 + b_n) * 80u
                               + (uint32_t)(k0 + b_k8) * 2u;
                LDM_X4(bh[0], bh[1], bh[2], bh[3], baddr);
                LDM_X4(bl[0], bl[1], bl[2], bl[3], baddr + TILE_B);

#pragma unroll
                for (int h = 0; h < 2; h++) {
                    uint32_t bfh[2] = { bh[2*h], bh[2*h + 1] };
                    uint32_t bfl[2] = { bl[2*h], bl[2*h + 1] };
                    const int nt = nt2 * 2 + h;
#pragma unroll
                    for (int mt = 0; mt < 2; mt++) {
                        MMA_BF16(acc[mt][nt], ah[mt], bfh);
                        MMA_BF16(acc[mt][nt], ah[mt], bfl);
                        MMA_BF16(acc[mt][nt], al[mt], bfh);
                    }
                }
            }
        }
        __syncthreads();
    }

    const int g  = lane >> 2;
    const int tI = lane & 3;
#pragma unroll
    for (int mt = 0; mt < 2; mt++) {
        const int row0 = m0 + wm*32 + mt*16 + g;
#pragma unroll
        for (int nt = 0; nt < 8; nt++) {
            const int col = n0 + wn*64 + nt*8 + tI*2;
            float2 bb = *(const float2*)&bias[col];
            float v00 = acc[mt][nt][0] + bb.x, v01 = acc[mt][nt][1] + bb.y;
            float v10 = acc[mt][nt][2] + bb.x, v11 = acc[mt][nt][3] + bb.y;
            if (!SPLIT) {
                *(float2*)(C + (size_t)row0       * N + col) = make_float2(v00, v01);
                *(float2*)(C + (size_t)(row0 + 8) * N + col) = make_float2(v10, v11);
            } else {
                __nv_bfloat16 h00 = __float2bfloat16(v00), h01 = __float2bfloat16(v01);
                __nv_bfloat16 h10 = __float2bfloat16(v10), h11 = __float2bfloat16(v11);
                *(uint32_t*)(Ch + (size_t)row0       * N + col) = packbf(__bfloat162float(h00)*0.f + v00*0.f + __bfloat162float(h00), __bfloat162float(h01));
                // (the above would be wrong; use direct packing below)
                *(uint32_t*)(Ch + (size_t)row0       * N + col) =
                    (uint32_t)*(uint16_t*)&h00 | ((uint32_t)*(uint16_t*)&h01 << 16);
                *(uint32_t*)(Ch + (size_t)(row0 + 8) * N + col) =
                    (uint32_t)*(uint16_t*)&h10 | ((uint32_t)*(uint16_t*)&h11 << 16);
                *(uint32_t*)(Cl + (size_t)row0       * N + col) =
                    packbf(v00 - __bfloat162float(h00), v01 - __bfloat162float(h01));
                *(uint32_t*)(Cl + (size_t)(row0 + 8) * N + col) =
                    packbf(v10 - __bfloat162float(h10), v11 - __bfloat162float(h11));
            }
        }
    }
}

// ---------------------------------------------------------------------------
// Flash attention with split-bf16 HMMA.  CTA = (qb: 128 q rows, b*h).
// 8 warps x 16 rows; each warp owns full kv width. P stays in registers.
// ---------------------------------------------------------------------------
#define FA_PITCH 72
#define FA_RB    (FA_PITCH * 2)          // 144 B row
#define FA_QH    0
#define FA_QL    (128 * FA_RB)           // 18432
#define FA_ST0   (2 * 128 * FA_RB)       // 36864
#define FA_TILE  (64 * FA_RB)            // 9216
#define FA_STAGE (4 * FA_TILE)           // 36864
#define FA_SMEM  (FA_ST0 + 2 * FA_STAGE) // 110592

__global__ __launch_bounds__(256, 1) void flash_mma(
    const __nv_bfloat16* __restrict__ Qh, const __nv_bfloat16* __restrict__ Ql,
    const __nv_bfloat16* __restrict__ Kh, const __nv_bfloat16* __restrict__ Kl,
    const __nv_bfloat16* __restrict__ Vh, const __nv_bfloat16* __restrict__ Vl,
    __nv_bfloat16* __restrict__ Ch, __nv_bfloat16* __restrict__ Cl)
{
    extern __shared__ char smem[];
    const uint32_t smem0 = smem_u32(smem);

    const int tid  = threadIdx.x;
    const int lane = tid & 31;
    const int wid  = tid >> 5;
    const int qb   = blockIdx.x;          // 0..15
    const int bh   = blockIdx.y;          // 0..63
    const int b    = bh >> 5;
    const int h    = bh & 31;

    const size_t qoff  = ((size_t)(b*Tt + qb*128)) * Dd + (size_t)h * HDh;
    const size_t kvoff = ((size_t)(b*Tt)) * Dd + (size_t)h * HDh;
    const __nv_bfloat16* kvsrc[4] = { Kh + kvoff, Kl + kvoff, Vh + kvoff, Vl + kvoff };

    const int a_r  = (lane & 7) + ((lane >> 3) & 1) * 8;
    const int a_k8 = (lane >> 4) * 8;
    const int b_n  = (lane & 7) + ((lane >> 4) ? 8 : 0);
    const int b_k8 = ((lane >> 3) & 1) * 8;
    const int v_c8 = ((lane >> 4) & 1) * 8;

    // ---- prologue: Q (both buffers) + KV stage 0 ----
#pragma unroll
    for (int it = 0; it < 8; it++) {
        int id  = it * 256 + tid;          // 0..2047
        int buf = id >> 10;                // 0: qh, 1: ql
        int r   = (id >> 3) & 127;
        int c   = id & 7;
        const __nv_bfloat16* src = (buf ? Ql : Qh) + qoff + (size_t)r * Dd + c * 8;
        CP_ASYNC16(smem0 + (buf ? FA_QL : FA_QH) + r * FA_RB + c * 16, src);
    }
#pragma unroll
    for (int it = 0; it < 8; it++) {
        int id  = it * 256 + tid;
        int buf = id >> 9;                 // 0..3: kh,kl,vh,vl
        int r   = (id >> 3) & 63;
        int c   = id & 7;
        CP_ASYNC16(smem0 + FA_ST0 + buf * FA_TILE + r * FA_RB + c * 16,
                   kvsrc[buf] + (size_t)r * Dd + c * 8);
    }
    CP_COMMIT();

    const int NT  = 2 * qb + 2;
    const int qr0 = qb * 128 + wid * 16;          // warp's first q row
    const int rowA = qr0 + (lane >> 2);
    const int rowB = rowA + 8;
    const float Cexp = 0.18033688011112042f;      // 0.125 * log2(e)

    float o[8][4];
#pragma unroll
    for (int j = 0; j < 8; j++)
#pragma unroll
        for (int i = 0; i < 4; i++) o[j][i] = 0.f;
    float mA = -1e30f, mB = -1e30f, lA = 0.f, lB = 0.f;

    uint32_t qhf[4][4], qlf[4][4];

    for (int kt = 0; kt < NT; kt++) {
        if (kt + 1 < NT) {
            const uint32_t st = smem0 + FA_ST0 + ((kt + 1) & 1) * FA_STAGE;
#pragma unroll
            for (int it = 0; it < 8; it++) {
                int id  = it * 256 + tid;
                int buf = id >> 9;
                int r   = (id >> 3) & 63;
                int c   = id & 7;
                CP_ASYNC16(st + buf * FA_TILE + r * FA_RB + c * 16,
                           kvsrc[buf] + (size_t)((kt + 1) * 64 + r) * Dd + c * 8);
            }
        }
        CP_COMMIT();
        CP_WAIT1();
        __syncthreads();

        if (kt == 0) {
#pragma unroll
            for (int k = 0; k < 4; k++) {
                uint32_t qa = smem0 + FA_QH + (uint32_t)(wid*16 + a_r) * FA_RB
                            + (uint32_t)(k*16 + a_k8) * 2u;
                LDM_X4(qhf[k][0], qhf[k][1], qhf[k][2], qhf[k][3], qa);
                LDM_X4(qlf[k][0], qlf[k][1], qlf[k][2], qlf[k][3], qa + FA_QL);
            }
        }

        const int kv0 = kt * 64;
        const uint32_t stg = smem0 + FA_ST0 + (kt & 1) * FA_STAGE;

        if (kv0 <= qr0 + 15) {              // warp has unmasked work in this tile
            // ---- S = Q K^T (3 passes) ----
            float s[8][4];
#pragma unroll
            for (int j = 0; j < 8; j++)
#pragma unroll
                for (int i = 0; i < 4; i++) s[j][i] = 0.f;

#pragma unroll
            for (int k = 0; k < 4; k++) {
#pragma unroll
                for (int j = 0; j < 4; j++) {
                    uint32_t kh4[4], kl4[4];
                    uint32_t ka = stg + (uint32_t)(j*16 + b_n) * FA_RB
                                + (uint32_t)(k*16 + b_k8) * 2u;
                    LDM_X4(kh4[0], kh4[1], kh4[2], kh4[3], ka);
                    LDM_X4(kl4[0], kl4[1], kl4[2], kl4[3], ka + FA_TILE);
#pragma unroll
                    for (int hh = 0; hh < 2; hh++) {
                        uint32_t bh2[2] = { kh4[2*hh], kh4[2*hh+1] };
                        uint32_t bl2[2] = { kl4[2*hh], kl4[2*hh+1] };
                        MMA_BF16(s[j*2 + hh], qhf[k], bh2);
                        MMA_BF16(s[j*2 + hh], qhf[k], bl2);
                        MMA_BF16(s[j*2 + hh], qlf[k], bh2);
                    }
                }
            }

            // ---- causal mask (only straddling tiles) ----
            if (kv0 + 63 > qr0) {
#pragma unroll
                for (int j = 0; j < 8; j++) {
                    int col = kv0 + j*8 + (lane & 3)*2;
                    if (col     > rowA) s[j][0] = -1e30f;
                    if (col + 1 > rowA) s[j][1] = -1e30f;
                    if (col     > rowB) s[j][2] = -1e30f;
                    if (col + 1 > rowB) s[j][3] = -1e30f;
                }
            }

            // ---- online softmax ----
            float mlA = s[0][0], mlB = s[0][2];
#pragma unroll
            for (int j = 0; j < 8; j++) {
                mlA = fmaxf(mlA, fmaxf(s[j][0], s[j][1]));
                mlB = fmaxf(mlB, fmaxf(s[j][2], s[j][3]));
            }
            mlA = fmaxf(mlA, __shfl_xor_sync(0xffffffffu, mlA, 1));
            mlA = fmaxf(mlA, __shfl_xor_sync(0xffffffffu, mlA, 2));
            mlB = fmaxf(mlB, __shfl_xor_sync(0xffffffffu, mlB, 1));
            mlB = fmaxf(mlB, __shfl_xor_sync(0xffffffffu, mlB, 2));

            float mnA = fmaxf(mA, mlA), mnB = fmaxf(mB, mlB);
            float aAlpha = ex2f((mA - mnA) * Cexp);
            float bAlpha = ex2f((mB - mnB) * Cexp);
            mA = mnA; mB = mnB;

            float psA = 0.f, psB = 0.f;
#pragma unroll
            for (int j = 0; j < 8; j++) {
                s[j][0] = ex2f((s[j][0] - mnA) * Cexp); psA += s[j][0];
                s[j][1] = ex2f((s[j][1] - mnA) * Cexp); psA += s[j][1];
                s[j][2] = ex2f((s[j][2] - mnB) * Cexp); psB += s[j][2];
                s[j][3] = ex2f((s[j][3] - mnB) * Cexp); psB += s[j][3];
            }
            lA = lA * aAlpha + psA;
            lB = lB * bAlpha + psB;
#pragma unroll
            for (int j = 0; j < 8; j++) {
                o[j][0] *= aAlpha; o[j][1] *= aAlpha;
                o[j][2] *= bAlpha; o[j][3] *= bAlpha;
            }

            // ---- pack P into hi/lo A-fragments ----
            uint32_t pa[4][4], pl[4][4];
#pragma unroll
            for (int kk = 0; kk < 4; kk++) {
#pragma unroll
                for (int half = 0; half < 2; half++) {
                    const int j = 2*kk + half;
                    __nv_bfloat16 h0 = __float2bfloat16(s[j][0]);
                    __nv_bfloat16 h1 = __float2bfloat16(s[j][1]);
                    __nv_bfloat16 h2 = __float2bfloat16(s[j][2]);
                    __nv_bfloat16 h3 = __float2bfloat16(s[j][3]);
                    pa[kk][0 + 2*half] =
                        (uint32_t)*(uint16_t*)&h0 | ((uint32_t)*(uint16_t*)&h1 << 16);
                    pa[kk][1 + 2*half] =
                        (uint32_t)*(uint16_t*)&h2 | ((uint32_t)*(uint16_t*)&h3 << 16);
                    pl[kk][0 + 2*half] = packbf(s[j][0] - __bfloat162float(h0),
                                                s[j][1] - __bfloat162float(h1));
                    pl[kk][1 + 2*half] = packbf(s[j][2] - __bfloat162float(h2),
                                                s[j][3] - __bfloat162float(h3));
                }
            }

            // ---- O += P V (3 passes) ----
#pragma unroll
            for (int kk = 0; kk < 4; kk++) {
#pragma unroll
                for (int j = 0; j < 4; j++) {
                    uint32_t vh4[4], vl4[4];
                    uint32_t va = stg + 2*FA_TILE + (uint32_t)(kk*16 + a_r) * FA_RB
                                + (uint32_t)(j*16 + v_c8) * 2u;
                    LDM_X4_T(vh4[0], vh4[1], vh4[2], vh4[3], va);
                    LDM_X4_T(vl4[0], vl4[1], vl4[2], vl4[3], va + FA_TILE);
#pragma unroll
                    for (int hh = 0; hh < 2; hh++) {
                        uint32_t bh2[2] = { vh4[2*hh], vh4[2*hh+1] };
                        uint32_t bl2[2] = { vl4[2*hh], vl4[2*hh+1] };
                        MMA_BF16(o[j*2 + hh], pa[kk], bh2);
                        MMA_BF16(o[j*2 + hh], pa[kk], bl2);
                        MMA_BF16(o[j*2 + hh], pl[kk], bh2);
                    }
                }
            }
        }
        __syncthreads();
    }

    // ---- epilogue: normalize, split to bf16 hi/lo, store ----
    lA += __shfl_xor_sync(0xffffffffu, lA, 1);
    lA += __shfl_xor_sync(0xffffffffu, lA, 2);
    lB += __shfl_xor_sync(0xffffffffu, lB, 1);
    lB += __shfl_xor_sync(0xffffffffu, lB, 2);
    const float invA = 1.f / lA, invB = 1.f / lB;

    const size_t obase = ((size_t)(b*Tt)) * Dd + (size_t)h * HDh;
#pragma unroll
    for (int j = 0; j < 8; j++) {
        const int col = j*8 + (lane & 3)*2;
        float vA0 = o[j][0] * invA, vA1 = o[j][1] * invA;
        float vB0 = o[j][2] * invB, vB1 = o[j][3] * invB;
        __nv_bfloat16 hA0 = __float2bfloat16(vA0), hA1 = __float2bfloat16(vA1);
        __nv_bfloat16 hB0 = __float2bfloat16(vB0), hB1 = __float2bfloat16(vB1);
        *(uint32_t*)(Ch + obase + (size_t)rowA * Dd + col) =
            (uint32_t)*(uint16_t*)&hA0 | ((uint32_t)*(uint16_t*)&hA1 << 16);
        *(uint32_t*)(Ch + obase + (size_t)rowB * Dd + col) =
            (uint32_t)*(uint16_t*)&hB0 | ((uint32_t)*(uint16_t*)&hB1 << 16);
        *(uint32_t*)(Cl + obase + (size_t)rowA * Dd + col) =
            packbf(vA0 - __bfloat162float(hA0), vA1 - __bfloat162float(hA1));
        *(uint32_t*)(Cl + obase + (size_t)rowB * Dd + col) =
            packbf(vB0 - __bfloat162float(hB0), vB1 - __bfloat162float(hB1));
    }
}

// ---------------------------------------------------------------------------
extern "C" void kernel_launch(void* const* d_in, const int* in_sizes, int n_in,
                              void* d_out, int out_size)
{
    const float* x  = (const float*)d_in[0];
    const float* Wq = (const float*)d_in[1];
    const float* bq = (const float*)d_in[2];
    const float* Wk = (const float*)d_in[3];
    const float* bk = (const float*)d_in[4];
    const float* Wv = (const float*)d_in[5];
    const float* bv = (const float*)d_in[6];
    const float* Wo = (const float*)d_in[7];
    const float* bo = (const float*)d_in[8];
    float* out = (float*)d_out;

    __nv_bfloat16 *xh, *xl, *ch, *cl;
    __nv_bfloat16 *wqh, *wql, *wkh, *wkl, *wvh, *wvl, *woh, *wol;
    __nv_bfloat16 *aqh, *aql, *akh, *akl, *avh, *avl;
    cudaGetSymbolAddress((void**)&xh, g_xh);   cudaGetSymbolAddress((void**)&xl, g_xl);
    cudaGetSymbolAddress((void**)&ch, g_ch);   cudaGetSymbolAddress((void**)&cl, g_cl);
    cudaGetSymbolAddress((void**)&wqh, g_wqh); cudaGetSymbolAddress((void**)&wql, g_wql);
    cudaGetSymbolAddress((void**)&wkh, g_wkh); cudaGetSymbolAddress((void**)&wkl, g_wkl);
    cudaGetSymbolAddress((void**)&wvh, g_wvh); cudaGetSymbolAddress((void**)&wvl, g_wvl);
    cudaGetSymbolAddress((void**)&woh, g_woh); cudaGetSymbolAddress((void**)&wol, g_wol);
    cudaGetSymbolAddress((void**)&aqh, g_aqh); cudaGetSymbolAddress((void**)&aql, g_aql);
    cudaGetSymbolAddress((void**)&akh, g_akh); cudaGetSymbolAddress((void**)&akl, g_akl);
    cudaGetSymbolAddress((void**)&avh, g_avh); cudaGetSymbolAddress((void**)&avl, g_avl);

    cudaFuncSetAttribute(gemm_split_mma<false>,
                         cudaFuncAttributeMaxDynamicSharedMemorySize, GEMM_SMEM);
    cudaFuncSetAttribute(gemm_split_mma<true>,
                         cudaFuncAttributeMaxDynamicSharedMemorySize, GEMM_SMEM);
    cudaFuncSetAttribute(flash_mma,
                         cudaFuncAttributeMaxDynamicSharedMemorySize, FA_SMEM);

    const int nX4 = Mtot * Dd / 4;
    const int nW4 = Dd * Dd / 4;
    split_bf16<<<nX4 / 256, 256>>>(x,  xh,  xl,  nX4);
    split_bf16<<<nW4 / 256, 256>>>(Wq, wqh, wql, nW4);
    split_bf16<<<nW4 / 256, 256>>>(Wk, wkh, wkl, nW4);
    split_bf16<<<nW4 / 256, 256>>>(Wv, wvh, wvl, nW4);
    split_bf16<<<nW4 / 256, 256>>>(Wo, woh, wol, nW4);

    dim3 gP(Dd / BN, Mtot / BM);     // (16, 32)
    gemm_split_mma<true><<<gP, 256, GEMM_SMEM>>>(
        xh, xl, wqh, wql, bq, nullptr, aqh, aql, Mtot, Dd, Dd);
    gemm_split_mma<true><<<gP, 256, GEMM_SMEM>>>(
        xh, xl, wkh, wkl, bk, nullptr, akh, akl, Mtot, Dd, Dd);
    gemm_split_mma<true><<<gP, 256, GEMM_SMEM>>>(
        xh, xl, wvh, wvl, bv, nullptr, avh, avl, Mtot, Dd, Dd);

    dim3 gA(Tt / 128, Bb * Hh);      // (16, 64)
    flash_mma<<<gA, 256, FA_SMEM>>>(aqh, aql, akh, akl, avh, avl, ch, cl);

    gemm_split_mma<false><<<gP, 256, GEMM_SMEM>>>(
        ch, cl, woh, wol, bo, out, nullptr, nullptr, Mtot, Dd, Dd);
}